// round 2
// baseline (speedup 1.0000x reference)
#include <cuda_runtime.h>
#include <math.h>

// Problem dims
#define B_   32
#define N_   3136
#define C_   384
#define H_   8
#define DH_  48
#define M_   196
#define T_   (B_ * N_)          // 100352 tokens

// ---------------- scratch (static device globals; no runtime allocation) ---
__device__ float g_xg[T_ * C_];              // gelu(ln(x))        154 MB
__device__ float g_k [B_ * H_ * N_ * DH_];   // k in [b,h,n,d]     154 MB
__device__ float g_v [B_ * H_ * N_ * DH_];   // v in [b,h,n,d]     154 MB
__device__ float g_ao[B_ * M_ * C_];         // attn out [b,m,c]   9.6 MB

// ---------------------------------------------------------------- K1: LN+GELU
// One CTA (128 threads) per token. var via E[x^2]-mu^2 (|x|~1, no cancellation).
__global__ __launch_bounds__(128) void ln_gelu_kernel(
    const float* __restrict__ x,
    const float* __restrict__ lw,
    const float* __restrict__ lb)
{
    int t = blockIdx.x;
    const float* xr = x + (size_t)t * C_;
    float* outr = g_xg + (size_t)t * C_;
    int tid = threadIdx.x;

    float v0 = xr[tid], v1 = xr[tid + 128], v2 = xr[tid + 256];
    float s  = v0 + v1 + v2;
    float sq = v0 * v0 + v1 * v1 + v2 * v2;
    #pragma unroll
    for (int o = 16; o > 0; o >>= 1) {
        s  += __shfl_down_sync(0xffffffffu, s,  o);
        sq += __shfl_down_sync(0xffffffffu, sq, o);
    }
    __shared__ float ss[4], sqs[4];
    __shared__ float mu_s, rs_s;
    int w = tid >> 5;
    if ((tid & 31) == 0) { ss[w] = s; sqs[w] = sq; }
    __syncthreads();
    if (tid == 0) {
        float S  = ss[0] + ss[1] + ss[2] + ss[3];
        float SQ = sqs[0] + sqs[1] + sqs[2] + sqs[3];
        float mu  = S * (1.0f / C_);
        float var = SQ * (1.0f / C_) - mu * mu;
        mu_s = mu;
        rs_s = rsqrtf(var + 1e-6f);
    }
    __syncthreads();
    float mu = mu_s, rs = rs_s;

    #pragma unroll
    for (int i = 0; i < 3; i++) {
        int c = tid + i * 128;
        float v = (i == 0) ? v0 : ((i == 1) ? v1 : v2);
        float y = (v - mu) * rs * lw[c] + lb[c];
        // exact GELU: 0.5*y*(1+erf(y/sqrt(2)))
        float g = 0.5f * y * (1.0f + erff(y * 0.70710678118654752f));
        outr[c] = g;
    }
}

// --------------------------------------------------------- K2: kv SGEMM
// out[t, j] = sum_c xg[t,c] * kv_w[j,c],  M=100352, N=768, K=384.
// 128x128 tile, 256 threads, 8x8 per thread. Epilogue scatters into
// g_k / g_v with layout [b,h,n,d] for contiguous attention reads.
__global__ __launch_bounds__(256) void sgemm_kv_kernel(const float* __restrict__ W)
{
    __shared__ __align__(16) float As[8][136];
    __shared__ __align__(16) float Bs[8][136];

    int n0 = blockIdx.x * 128;   // 6 column tiles (x fastest -> L2 reuse of A)
    int m0 = blockIdx.y * 128;   // 784 row tiles
    int tid = threadIdx.x;
    int tx = tid & 15, ty = tid >> 4;
    int lrow = tid >> 1;
    int lk   = (tid & 1) * 4;

    const float* aptr = g_xg + (size_t)(m0 + lrow) * C_ + lk;
    const float* wptr = W    + (size_t)(n0 + lrow) * C_ + lk;

    float acc[8][8];
    #pragma unroll
    for (int i = 0; i < 8; i++)
        #pragma unroll
        for (int j = 0; j < 8; j++) acc[i][j] = 0.0f;

    for (int k0 = 0; k0 < C_; k0 += 8) {
        float4 av = *(const float4*)(aptr + k0);
        float4 bv = *(const float4*)(wptr + k0);
        __syncthreads();
        As[lk + 0][lrow] = av.x; As[lk + 1][lrow] = av.y;
        As[lk + 2][lrow] = av.z; As[lk + 3][lrow] = av.w;
        Bs[lk + 0][lrow] = bv.x; Bs[lk + 1][lrow] = bv.y;
        Bs[lk + 2][lrow] = bv.z; Bs[lk + 3][lrow] = bv.w;
        __syncthreads();
        #pragma unroll
        for (int kk = 0; kk < 8; kk++) {
            float a[8], b[8];
            *(float4*)&a[0] = *(const float4*)&As[kk][ty * 4];
            *(float4*)&a[4] = *(const float4*)&As[kk][64 + ty * 4];
            *(float4*)&b[0] = *(const float4*)&Bs[kk][tx * 4];
            *(float4*)&b[4] = *(const float4*)&Bs[kk][64 + tx * 4];
            #pragma unroll
            for (int i = 0; i < 8; i++)
                #pragma unroll
                for (int j = 0; j < 8; j++)
                    acc[i][j] += a[i] * b[j];
        }
    }

    // scatter epilogue: col c -> (k|v, h, d); row r -> (b, n)
    #pragma unroll
    for (int i = 0; i < 8; i++) {
        int r  = m0 + ((i < 4) ? (ty * 4 + i) : (64 + ty * 4 + i - 4));
        int bb = r / N_;
        int nn = r - bb * N_;
        #pragma unroll
        for (int j = 0; j < 8; j++) {
            int c  = n0 + ((j < 4) ? (tx * 4 + j) : (64 + tx * 4 + j - 4));
            int cc = (c >= C_) ? (c - C_) : c;
            int h  = cc / DH_;
            int d  = cc - h * DH_;
            float* dst = (c >= C_) ? g_v : g_k;
            dst[(((size_t)bb * H_ + h) * N_ + nn) * DH_ + d] = acc[i][j];
        }
    }
}

// ------------------------------------------------------------- K3: attention
// One CTA per (b,h). 224 threads; threads 0..195 each own one query row m.
// q row lives in registers; k/v streamed through smem in 112-row tiles.
// Logits are tiny (q scaled 0.02) -> unshifted exp == reference softmax.
#define TN 112
__global__ __launch_bounds__(224) void attn_kernel(const float* __restrict__ qp)
{
    __shared__ float ks[TN * DH_];
    __shared__ float vs[TN * DH_];

    int bh = blockIdx.x;
    int b = bh >> 3, h = bh & 7;
    int tid = threadIdx.x;
    bool active = tid < M_;

    float q[DH_];
    if (active) {
        #pragma unroll
        for (int d = 0; d < DH_; d++)
            q[d] = qp[((size_t)tid * H_ + h) * DH_ + d];   // q_param[0,m,h,d]
    }
    float acc[DH_];
    #pragma unroll
    for (int d = 0; d < DH_; d++) acc[d] = 0.0f;
    float lsum = 0.0f;

    const float* kbase = g_k + (size_t)bh * N_ * DH_;
    const float* vbase = g_v + (size_t)bh * N_ * DH_;

    for (int t0 = 0; t0 < N_; t0 += TN) {
        const float4* ksrc = (const float4*)(kbase + (size_t)t0 * DH_);
        const float4* vsrc = (const float4*)(vbase + (size_t)t0 * DH_);
        #pragma unroll
        for (int i = 0; i < (TN * DH_ / 4) / 224; i++) {   // 6 iters
            int idx = tid + i * 224;
            ((float4*)ks)[idx] = ksrc[idx];
            ((float4*)vs)[idx] = vsrc[idx];
        }
        __syncthreads();
        if (active) {
            #pragma unroll 2
            for (int n = 0; n < TN; n++) {
                const float* kr = ks + n * DH_;
                float s0 = 0.f, s1 = 0.f, s2 = 0.f, s3 = 0.f;
                #pragma unroll
                for (int d4 = 0; d4 < DH_ / 4; d4++) {
                    float4 k4 = *(const float4*)(kr + d4 * 4);
                    s0 += q[d4 * 4 + 0] * k4.x;
                    s1 += q[d4 * 4 + 1] * k4.y;
                    s2 += q[d4 * 4 + 2] * k4.z;
                    s3 += q[d4 * 4 + 3] * k4.w;
                }
                float p = __expf((s0 + s1) + (s2 + s3));
                lsum += p;
                const float* vr = vs + n * DH_;
                #pragma unroll
                for (int d4 = 0; d4 < DH_ / 4; d4++) {
                    float4 v4 = *(const float4*)(vr + d4 * 4);
                    acc[d4 * 4 + 0] += p * v4.x;
                    acc[d4 * 4 + 1] += p * v4.y;
                    acc[d4 * 4 + 2] += p * v4.z;
                    acc[d4 * 4 + 3] += p * v4.w;
                }
            }
        }
        __syncthreads();
    }

    if (active) {
        float inv = 1.0f / lsum;
        float* orow = g_ao + ((size_t)b * M_ + tid) * C_ + h * DH_;
        #pragma unroll
        for (int d = 0; d < DH_; d++) orow[d] = acc[d] * inv;
    }
}

// -------------------------------------------------------------- K4: proj GEMM
// out[r, c] = sum_k g_ao[r,k] * proj_w[c,k] + proj_b[c],  M=6272, N=384, K=384
__global__ __launch_bounds__(256) void sgemm_proj_kernel(
    const float* __restrict__ W,
    const float* __restrict__ bias,
    float* __restrict__ out)
{
    __shared__ __align__(16) float As[8][136];
    __shared__ __align__(16) float Bs[8][136];

    int n0 = blockIdx.x * 128;   // 3 tiles
    int m0 = blockIdx.y * 128;   // 49 tiles
    int tid = threadIdx.x;
    int tx = tid & 15, ty = tid >> 4;
    int lrow = tid >> 1;
    int lk   = (tid & 1) * 4;

    const float* aptr = g_ao + (size_t)(m0 + lrow) * C_ + lk;
    const float* wptr = W    + (size_t)(n0 + lrow) * C_ + lk;

    float acc[8][8];
    #pragma unroll
    for (int i = 0; i < 8; i++)
        #pragma unroll
        for (int j = 0; j < 8; j++) acc[i][j] = 0.0f;

    for (int k0 = 0; k0 < C_; k0 += 8) {
        float4 av = *(const float4*)(aptr + k0);
        float4 bv = *(const float4*)(wptr + k0);
        __syncthreads();
        As[lk + 0][lrow] = av.x; As[lk + 1][lrow] = av.y;
        As[lk + 2][lrow] = av.z; As[lk + 3][lrow] = av.w;
        Bs[lk + 0][lrow] = bv.x; Bs[lk + 1][lrow] = bv.y;
        Bs[lk + 2][lrow] = bv.z; Bs[lk + 3][lrow] = bv.w;
        __syncthreads();
        #pragma unroll
        for (int kk = 0; kk < 8; kk++) {
            float a[8], b[8];
            *(float4*)&a[0] = *(const float4*)&As[kk][ty * 4];
            *(float4*)&a[4] = *(const float4*)&As[kk][64 + ty * 4];
            *(float4*)&b[0] = *(const float4*)&Bs[kk][tx * 4];
            *(float4*)&b[4] = *(const float4*)&Bs[kk][64 + tx * 4];
            #pragma unroll
            for (int i = 0; i < 8; i++)
                #pragma unroll
                for (int j = 0; j < 8; j++)
                    acc[i][j] += a[i] * b[j];
        }
    }

    #pragma unroll
    for (int i = 0; i < 8; i++) {
        int r = m0 + ((i < 4) ? (ty * 4 + i) : (64 + ty * 4 + i - 4));
        #pragma unroll
        for (int j = 0; j < 8; j++) {
            int c = n0 + ((j < 4) ? (tx * 4 + j) : (64 + tx * 4 + j - 4));
            out[(size_t)r * C_ + c] = acc[i][j] + bias[c];
        }
    }
}

// ----------------------------------------------------------------- launcher
extern "C" void kernel_launch(void* const* d_in, const int* in_sizes, int n_in,
                              void* d_out, int out_size)
{
    const float* x      = (const float*)d_in[0];
    const float* qp     = (const float*)d_in[1];
    const float* kv_w   = (const float*)d_in[2];
    const float* proj_w = (const float*)d_in[3];
    const float* proj_b = (const float*)d_in[4];
    const float* ln_w   = (const float*)d_in[5];
    const float* ln_b   = (const float*)d_in[6];
    float* out = (float*)d_out;

    ln_gelu_kernel<<<T_, 128>>>(x, ln_w, ln_b);

    dim3 g2(6, 784);                    // x = col tile (6) fastest -> A L2 reuse
    sgemm_kv_kernel<<<g2, 256>>>(kv_w);

    attn_kernel<<<B_ * H_, 224>>>(qp);

    dim3 g4(3, 49);
    sgemm_proj_kernel<<<g4, 256>>>(proj_w, proj_b, out);
}

// round 3
// speedup vs baseline: 1.5748x; 1.5748x over previous
#include <cuda_runtime.h>
#include <math.h>

// Problem dims
#define B_   32
#define N_   3136
#define C_   384
#define H_   8
#define DH_  48
#define M_   196
#define T_   (B_ * N_)          // 100352 tokens

// ---------------- scratch (static device globals; no runtime allocation) ---
__device__ float g_xg[T_ * C_];              // gelu(ln(x))        154 MB
__device__ float g_k [B_ * H_ * N_ * DH_];   // k in [b,h,n,d]     154 MB
__device__ float g_v [B_ * H_ * N_ * DH_];   // v in [b,h,n,d]     154 MB
__device__ float g_ao[B_ * M_ * C_];         // attn out [b,m,c]   9.6 MB

// ---------------------------------------------------------------- K1: LN+GELU
__global__ __launch_bounds__(128) void ln_gelu_kernel(
    const float* __restrict__ x,
    const float* __restrict__ lw,
    const float* __restrict__ lb)
{
    int t = blockIdx.x;
    const float* xr = x + (size_t)t * C_;
    float* outr = g_xg + (size_t)t * C_;
    int tid = threadIdx.x;

    float v0 = xr[tid], v1 = xr[tid + 128], v2 = xr[tid + 256];
    float s  = v0 + v1 + v2;
    float sq = v0 * v0 + v1 * v1 + v2 * v2;
    #pragma unroll
    for (int o = 16; o > 0; o >>= 1) {
        s  += __shfl_down_sync(0xffffffffu, s,  o);
        sq += __shfl_down_sync(0xffffffffu, sq, o);
    }
    __shared__ float ss[4], sqs[4];
    __shared__ float mu_s, rs_s;
    int w = tid >> 5;
    if ((tid & 31) == 0) { ss[w] = s; sqs[w] = sq; }
    __syncthreads();
    if (tid == 0) {
        float S  = ss[0] + ss[1] + ss[2] + ss[3];
        float SQ = sqs[0] + sqs[1] + sqs[2] + sqs[3];
        float mu  = S * (1.0f / C_);
        float var = SQ * (1.0f / C_) - mu * mu;
        mu_s = mu;
        rs_s = rsqrtf(var + 1e-6f);
    }
    __syncthreads();
    float mu = mu_s, rs = rs_s;

    #pragma unroll
    for (int i = 0; i < 3; i++) {
        int c = tid + i * 128;
        float v = (i == 0) ? v0 : ((i == 1) ? v1 : v2);
        float y = (v - mu) * rs * lw[c] + lb[c];
        float g = 0.5f * y * (1.0f + erff(y * 0.70710678118654752f));
        outr[c] = g;
    }
}

// ------------------------------------------------------ tf32 MMA helpers
__device__ __forceinline__ unsigned f2tf32(float f) {
    unsigned r;
    asm("cvt.rna.tf32.f32 %0, %1;" : "=r"(r) : "f"(f));
    return r;
}

__device__ __forceinline__ void mma_tf32(float* c, const unsigned* a, const unsigned* b) {
    asm volatile(
        "mma.sync.aligned.m16n8k8.row.col.f32.tf32.tf32.f32 "
        "{%0,%1,%2,%3}, {%4,%5,%6,%7}, {%8,%9}, {%0,%1,%2,%3};"
        : "+f"(c[0]), "+f"(c[1]), "+f"(c[2]), "+f"(c[3])
        : "r"(a[0]), "r"(a[1]), "r"(a[2]), "r"(a[3]),
          "r"(b[0]), "r"(b[1]));
}

// --------------------------------------------------------- K2: kv GEMM (tf32)
// out[t, j] = sum_c xg[t,c] * kv_w[j,c],  M=100352, N=768, K=384.
// CTA 128x128, 8 warps in 2(M)x4(N), warp tile 64x32, m16n8k8 tf32 mma.
// Epilogue scatters into g_k / g_v with layout [b,h,n,d].
__global__ __launch_bounds__(256) void mma_kv_kernel(const float* __restrict__ W)
{
    // [k][row] layout; 136 stride => k-stride mod 32 == 8 -> conflict-free frags
    __shared__ unsigned As[16][136];
    __shared__ unsigned Bs[16][136];

    int n0 = blockIdx.x * 128;   // 6 col tiles (x fastest -> A L2 reuse)
    int m0 = blockIdx.y * 128;   // 784 row tiles
    int tid = threadIdx.x;
    int wid = tid >> 5, lane = tid & 31;
    int wm = wid >> 2;           // 0..1  (M warp)
    int wn = wid & 3;            // 0..3  (N warp)
    int fr = lane >> 2;          // 0..7
    int fk = lane & 3;           // 0..3

    int lrow = tid >> 1;         // 0..127
    int lkh  = (tid & 1) * 8;    // 0 or 8

    const float* aptr = g_xg + (size_t)(m0 + lrow) * C_ + lkh;
    const float* wptr = W    + (size_t)(n0 + lrow) * C_ + lkh;

    float acc[4][4][4];          // [mt][nt][creg]
    #pragma unroll
    for (int i = 0; i < 4; i++)
        #pragma unroll
        for (int j = 0; j < 4; j++)
            #pragma unroll
            for (int r = 0; r < 4; r++) acc[i][j][r] = 0.0f;

    for (int k0 = 0; k0 < C_; k0 += 16) {
        float4 a0 = *(const float4*)(aptr + k0);
        float4 a1 = *(const float4*)(aptr + k0 + 4);
        float4 b0 = *(const float4*)(wptr + k0);
        float4 b1 = *(const float4*)(wptr + k0 + 4);
        __syncthreads();
        As[lkh + 0][lrow] = f2tf32(a0.x); As[lkh + 1][lrow] = f2tf32(a0.y);
        As[lkh + 2][lrow] = f2tf32(a0.z); As[lkh + 3][lrow] = f2tf32(a0.w);
        As[lkh + 4][lrow] = f2tf32(a1.x); As[lkh + 5][lrow] = f2tf32(a1.y);
        As[lkh + 6][lrow] = f2tf32(a1.z); As[lkh + 7][lrow] = f2tf32(a1.w);
        Bs[lkh + 0][lrow] = f2tf32(b0.x); Bs[lkh + 1][lrow] = f2tf32(b0.y);
        Bs[lkh + 2][lrow] = f2tf32(b0.z); Bs[lkh + 3][lrow] = f2tf32(b0.w);
        Bs[lkh + 4][lrow] = f2tf32(b1.x); Bs[lkh + 5][lrow] = f2tf32(b1.y);
        Bs[lkh + 6][lrow] = f2tf32(b1.z); Bs[lkh + 7][lrow] = f2tf32(b1.w);
        __syncthreads();

        #pragma unroll
        for (int kp = 0; kp < 16; kp += 8) {
            unsigned af[4][4];
            #pragma unroll
            for (int mt = 0; mt < 4; mt++) {
                int row = wm * 64 + mt * 16 + fr;
                af[mt][0] = As[kp + fk    ][row    ];
                af[mt][1] = As[kp + fk    ][row + 8];
                af[mt][2] = As[kp + fk + 4][row    ];
                af[mt][3] = As[kp + fk + 4][row + 8];
            }
            unsigned bf[4][2];
            #pragma unroll
            for (int nt = 0; nt < 4; nt++) {
                int col = wn * 32 + nt * 8 + fr;
                bf[nt][0] = Bs[kp + fk    ][col];
                bf[nt][1] = Bs[kp + fk + 4][col];
            }
            #pragma unroll
            for (int mt = 0; mt < 4; mt++)
                #pragma unroll
                for (int nt = 0; nt < 4; nt++)
                    mma_tf32(acc[mt][nt], af[mt], bf[nt]);
        }
    }

    // Epilogue: row r -> (b, n); col c -> (k|v, h, d). Cols (c, c+1) are always
    // in the same head (8-aligned blocks, 48 % 8 == 0) -> float2 stores.
    #pragma unroll
    for (int mt = 0; mt < 4; mt++) {
        #pragma unroll
        for (int half = 0; half < 2; half++) {
            int r  = m0 + wm * 64 + mt * 16 + fr + half * 8;
            int bb = r / N_;
            int nn = r - bb * N_;
            #pragma unroll
            for (int nt = 0; nt < 4; nt++) {
                int c  = n0 + wn * 32 + nt * 8 + fk * 2;
                int cc = (c >= C_) ? (c - C_) : c;
                int h  = cc / DH_;
                int d  = cc - h * DH_;
                float* dst = (c >= C_) ? g_v : g_k;
                float2 val;
                val.x = acc[mt][nt][half * 2 + 0];
                val.y = acc[mt][nt][half * 2 + 1];
                *(float2*)(dst + (((size_t)bb * H_ + h) * N_ + nn) * DH_ + d) = val;
            }
        }
    }
}

// ------------------------------------------------------------- K3: attention
#define TN 112
__global__ __launch_bounds__(224) void attn_kernel(const float* __restrict__ qp)
{
    __shared__ float ks[TN * DH_];
    __shared__ float vs[TN * DH_];

    int bh = blockIdx.x;
    int b = bh >> 3, h = bh & 7;
    int tid = threadIdx.x;
    bool active = tid < M_;

    float q[DH_];
    if (active) {
        #pragma unroll
        for (int d = 0; d < DH_; d++)
            q[d] = qp[((size_t)tid * H_ + h) * DH_ + d];
    }
    float acc[DH_];
    #pragma unroll
    for (int d = 0; d < DH_; d++) acc[d] = 0.0f;
    float lsum = 0.0f;

    const float* kbase = g_k + (size_t)bh * N_ * DH_;
    const float* vbase = g_v + (size_t)bh * N_ * DH_;

    for (int t0 = 0; t0 < N_; t0 += TN) {
        const float4* ksrc = (const float4*)(kbase + (size_t)t0 * DH_);
        const float4* vsrc = (const float4*)(vbase + (size_t)t0 * DH_);
        #pragma unroll
        for (int i = 0; i < (TN * DH_ / 4) / 224; i++) {
            int idx = tid + i * 224;
            ((float4*)ks)[idx] = ksrc[idx];
            ((float4*)vs)[idx] = vsrc[idx];
        }
        __syncthreads();
        if (active) {
            #pragma unroll 2
            for (int n = 0; n < TN; n++) {
                const float* kr = ks + n * DH_;
                float s0 = 0.f, s1 = 0.f, s2 = 0.f, s3 = 0.f;
                #pragma unroll
                for (int d4 = 0; d4 < DH_ / 4; d4++) {
                    float4 k4 = *(const float4*)(kr + d4 * 4);
                    s0 += q[d4 * 4 + 0] * k4.x;
                    s1 += q[d4 * 4 + 1] * k4.y;
                    s2 += q[d4 * 4 + 2] * k4.z;
                    s3 += q[d4 * 4 + 3] * k4.w;
                }
                float p = __expf((s0 + s1) + (s2 + s3));
                lsum += p;
                const float* vr = vs + n * DH_;
                #pragma unroll
                for (int d4 = 0; d4 < DH_ / 4; d4++) {
                    float4 v4 = *(const float4*)(vr + d4 * 4);
                    acc[d4 * 4 + 0] += p * v4.x;
                    acc[d4 * 4 + 1] += p * v4.y;
                    acc[d4 * 4 + 2] += p * v4.z;
                    acc[d4 * 4 + 3] += p * v4.w;
                }
            }
        }
        __syncthreads();
    }

    if (active) {
        float inv = 1.0f / lsum;
        float* orow = g_ao + ((size_t)b * M_ + tid) * C_ + h * DH_;
        #pragma unroll
        for (int d = 0; d < DH_; d++) orow[d] = acc[d] * inv;
    }
}

// -------------------------------------------------------------- K4: proj GEMM
__global__ __launch_bounds__(256) void sgemm_proj_kernel(
    const float* __restrict__ W,
    const float* __restrict__ bias,
    float* __restrict__ out)
{
    __shared__ __align__(16) float As[8][136];
    __shared__ __align__(16) float Bs[8][136];

    int n0 = blockIdx.x * 128;
    int m0 = blockIdx.y * 128;
    int tid = threadIdx.x;
    int tx = tid & 15, ty = tid >> 4;
    int lrow = tid >> 1;
    int lk   = (tid & 1) * 4;

    const float* aptr = g_ao + (size_t)(m0 + lrow) * C_ + lk;
    const float* wptr = W    + (size_t)(n0 + lrow) * C_ + lk;

    float acc[8][8];
    #pragma unroll
    for (int i = 0; i < 8; i++)
        #pragma unroll
        for (int j = 0; j < 8; j++) acc[i][j] = 0.0f;

    for (int k0 = 0; k0 < C_; k0 += 8) {
        float4 av = *(const float4*)(aptr + k0);
        float4 bv = *(const float4*)(wptr + k0);
        __syncthreads();
        As[lk + 0][lrow] = av.x; As[lk + 1][lrow] = av.y;
        As[lk + 2][lrow] = av.z; As[lk + 3][lrow] = av.w;
        Bs[lk + 0][lrow] = bv.x; Bs[lk + 1][lrow] = bv.y;
        Bs[lk + 2][lrow] = bv.z; Bs[lk + 3][lrow] = bv.w;
        __syncthreads();
        #pragma unroll
        for (int kk = 0; kk < 8; kk++) {
            float a[8], b[8];
            *(float4*)&a[0] = *(const float4*)&As[kk][ty * 4];
            *(float4*)&a[4] = *(const float4*)&As[kk][64 + ty * 4];
            *(float4*)&b[0] = *(const float4*)&Bs[kk][tx * 4];
            *(float4*)&b[4] = *(const float4*)&Bs[kk][64 + tx * 4];
            #pragma unroll
            for (int i = 0; i < 8; i++)
                #pragma unroll
                for (int j = 0; j < 8; j++)
                    acc[i][j] += a[i] * b[j];
        }
    }

    #pragma unroll
    for (int i = 0; i < 8; i++) {
        int r = m0 + ((i < 4) ? (ty * 4 + i) : (64 + ty * 4 + i - 4));
        #pragma unroll
        for (int j = 0; j < 8; j++) {
            int c = n0 + ((j < 4) ? (tx * 4 + j) : (64 + tx * 4 + j - 4));
            out[(size_t)r * C_ + c] = acc[i][j] + bias[c];
        }
    }
}

// ----------------------------------------------------------------- launcher
extern "C" void kernel_launch(void* const* d_in, const int* in_sizes, int n_in,
                              void* d_out, int out_size)
{
    const float* x      = (const float*)d_in[0];
    const float* qp     = (const float*)d_in[1];
    const float* kv_w   = (const float*)d_in[2];
    const float* proj_w = (const float*)d_in[3];
    const float* proj_b = (const float*)d_in[4];
    const float* ln_w   = (const float*)d_in[5];
    const float* ln_b   = (const float*)d_in[6];
    float* out = (float*)d_out;

    ln_gelu_kernel<<<T_, 128>>>(x, ln_w, ln_b);

    dim3 g2(6, 784);
    mma_kv_kernel<<<g2, 256>>>(kv_w);

    attn_kernel<<<B_ * H_, 224>>>(qp);

    dim3 g4(3, 49);
    sgemm_proj_kernel<<<g4, 256>>>(proj_w, proj_b, out);
}

// round 5
// speedup vs baseline: 2.5970x; 1.6491x over previous
#include <cuda_runtime.h>
#include <math.h>
#include <stdint.h>

// Problem dims
#define B_   32
#define N_   3136
#define C_   384
#define H_   8
#define DH_  48
#define M_   196
#define T_   (B_ * N_)          // 100352 tokens

// ---------------- scratch (static device globals; no runtime allocation) ---
__device__ float g_xg[T_ * C_];              // gelu(ln(x))        154 MB
__device__ float g_k [B_ * H_ * N_ * DH_];   // k in [b,h,n,d]     154 MB
__device__ float g_v [B_ * H_ * N_ * DH_];   // v in [b,h,n,d]     154 MB
__device__ float g_ao[B_ * M_ * C_];         // attn out [b,m,c]   9.6 MB

// ---------------------------------------------------------------- K1: LN+GELU
__global__ __launch_bounds__(128) void ln_gelu_kernel(
    const float* __restrict__ x,
    const float* __restrict__ lw,
    const float* __restrict__ lb)
{
    int t = blockIdx.x;
    const float* xr = x + (size_t)t * C_;
    float* outr = g_xg + (size_t)t * C_;
    int tid = threadIdx.x;

    float v0 = xr[tid], v1 = xr[tid + 128], v2 = xr[tid + 256];
    float s  = v0 + v1 + v2;
    float sq = v0 * v0 + v1 * v1 + v2 * v2;
    #pragma unroll
    for (int o = 16; o > 0; o >>= 1) {
        s  += __shfl_down_sync(0xffffffffu, s,  o);
        sq += __shfl_down_sync(0xffffffffu, sq, o);
    }
    __shared__ float ss[4], sqs[4];
    __shared__ float mu_s, rs_s;
    int w = tid >> 5;
    if ((tid & 31) == 0) { ss[w] = s; sqs[w] = sq; }
    __syncthreads();
    if (tid == 0) {
        float S  = ss[0] + ss[1] + ss[2] + ss[3];
        float SQ = sqs[0] + sqs[1] + sqs[2] + sqs[3];
        float mu  = S * (1.0f / C_);
        float var = SQ * (1.0f / C_) - mu * mu;
        mu_s = mu;
        rs_s = rsqrtf(var + 1e-6f);
    }
    __syncthreads();
    float mu = mu_s, rs = rs_s;

    #pragma unroll
    for (int i = 0; i < 3; i++) {
        int c = tid + i * 128;
        float v = (i == 0) ? v0 : ((i == 1) ? v1 : v2);
        float y = (v - mu) * rs * lw[c] + lb[c];
        float g = 0.5f * y * (1.0f + erff(y * 0.70710678118654752f));
        outr[c] = g;
    }
}

// ------------------------------------------------------ tf32 MMA helpers
__device__ __forceinline__ unsigned f2tf32(float f) {
    unsigned r;
    asm("cvt.rna.tf32.f32 %0, %1;" : "=r"(r) : "f"(f));
    return r;
}

__device__ __forceinline__ void mma_tf32(float* c, const unsigned* a, const unsigned* b) {
    asm volatile(
        "mma.sync.aligned.m16n8k8.row.col.f32.tf32.tf32.f32 "
        "{%0,%1,%2,%3}, {%4,%5,%6,%7}, {%8,%9}, {%0,%1,%2,%3};"
        : "+f"(c[0]), "+f"(c[1]), "+f"(c[2]), "+f"(c[3])
        : "r"(a[0]), "r"(a[1]), "r"(a[2]), "r"(a[3]),
          "r"(b[0]), "r"(b[1]));
}

__device__ __forceinline__ void cp16(uint32_t sa, const void* g) {
    asm volatile("cp.async.cg.shared.global [%0], [%1], 16;" :: "r"(sa), "l"(g));
}
#define CP_COMMIT() asm volatile("cp.async.commit_group;")
#define CP_WAIT1()  asm volatile("cp.async.wait_group 1;")
#define CP_WAIT0()  asm volatile("cp.async.wait_group 0;")

// --------------------------------------------------------- K2: kv GEMM (tf32)
// out[t, j] = sum_c xg[t,c] * kv_w[j,c],  M=100352, N=768, K=384.
// CTA 128x128, 8 warps 2x4, warp tile 64x32, m16n8k8 tf32 mma.
// Register-prefetch pipeline: LDG(next) issued before MMA(cur).
__global__ __launch_bounds__(256) void mma_kv_kernel(const float* __restrict__ W)
{
    __shared__ unsigned As[16][136];
    __shared__ unsigned Bs[16][136];

    int n0 = blockIdx.x * 128;
    int m0 = blockIdx.y * 128;
    int tid = threadIdx.x;
    int wid = tid >> 5, lane = tid & 31;
    int wm = wid >> 2;
    int wn = wid & 3;
    int fr = lane >> 2;
    int fk = lane & 3;

    int lrow = tid >> 1;
    int lkh  = (tid & 1) * 8;

    const float* aptr = g_xg + (size_t)(m0 + lrow) * C_ + lkh;
    const float* wptr = W    + (size_t)(n0 + lrow) * C_ + lkh;

    float acc[4][4][4];
    #pragma unroll
    for (int i = 0; i < 4; i++)
        #pragma unroll
        for (int j = 0; j < 4; j++)
            #pragma unroll
            for (int r = 0; r < 4; r++) acc[i][j][r] = 0.0f;

    // prologue loads (k0 = 0)
    float4 a0 = *(const float4*)(aptr);
    float4 a1 = *(const float4*)(aptr + 4);
    float4 b0 = *(const float4*)(wptr);
    float4 b1 = *(const float4*)(wptr + 4);

    for (int k0 = 0; k0 < C_; k0 += 16) {
        __syncthreads();
        As[lkh + 0][lrow] = f2tf32(a0.x); As[lkh + 1][lrow] = f2tf32(a0.y);
        As[lkh + 2][lrow] = f2tf32(a0.z); As[lkh + 3][lrow] = f2tf32(a0.w);
        As[lkh + 4][lrow] = f2tf32(a1.x); As[lkh + 5][lrow] = f2tf32(a1.y);
        As[lkh + 6][lrow] = f2tf32(a1.z); As[lkh + 7][lrow] = f2tf32(a1.w);
        Bs[lkh + 0][lrow] = f2tf32(b0.x); Bs[lkh + 1][lrow] = f2tf32(b0.y);
        Bs[lkh + 2][lrow] = f2tf32(b0.z); Bs[lkh + 3][lrow] = f2tf32(b0.w);
        Bs[lkh + 4][lrow] = f2tf32(b1.x); Bs[lkh + 5][lrow] = f2tf32(b1.y);
        Bs[lkh + 6][lrow] = f2tf32(b1.z); Bs[lkh + 7][lrow] = f2tf32(b1.w);
        __syncthreads();

        if (k0 + 16 < C_) {   // prefetch next iter (overlaps MMA below)
            a0 = *(const float4*)(aptr + k0 + 16);
            a1 = *(const float4*)(aptr + k0 + 20);
            b0 = *(const float4*)(wptr + k0 + 16);
            b1 = *(const float4*)(wptr + k0 + 20);
        }

        #pragma unroll
        for (int kp = 0; kp < 16; kp += 8) {
            unsigned af[4][4];
            #pragma unroll
            for (int mt = 0; mt < 4; mt++) {
                int row = wm * 64 + mt * 16 + fr;
                af[mt][0] = As[kp + fk    ][row    ];
                af[mt][1] = As[kp + fk    ][row + 8];
                af[mt][2] = As[kp + fk + 4][row    ];
                af[mt][3] = As[kp + fk + 4][row + 8];
            }
            unsigned bf[4][2];
            #pragma unroll
            for (int nt = 0; nt < 4; nt++) {
                int col = wn * 32 + nt * 8 + fr;
                bf[nt][0] = Bs[kp + fk    ][col];
                bf[nt][1] = Bs[kp + fk + 4][col];
            }
            #pragma unroll
            for (int mt = 0; mt < 4; mt++)
                #pragma unroll
                for (int nt = 0; nt < 4; nt++)
                    mma_tf32(acc[mt][nt], af[mt], bf[nt]);
        }
    }

    #pragma unroll
    for (int mt = 0; mt < 4; mt++) {
        #pragma unroll
        for (int half = 0; half < 2; half++) {
            int r  = m0 + wm * 64 + mt * 16 + fr + half * 8;
            int bb = r / N_;
            int nn = r - bb * N_;
            #pragma unroll
            for (int nt = 0; nt < 4; nt++) {
                int c  = n0 + wn * 32 + nt * 8 + fk * 2;
                int cc = (c >= C_) ? (c - C_) : c;
                int h  = cc / DH_;
                int d  = cc - h * DH_;
                float* dst = (c >= C_) ? g_v : g_k;
                float2 val;
                val.x = acc[mt][nt][half * 2 + 0];
                val.y = acc[mt][nt][half * 2 + 1];
                *(float2*)(dst + (((size_t)bb * H_ + h) * N_ + nn) * DH_ + d) = val;
            }
        }
    }
}

// ------------------------------------------------------------- K3: MMA attn
// One CTA (256 thr, 8 warps) per (b,h). Flash-style, tf32 mma.
// Q 208x48 (13 M-tiles, rows>=196 zero). K/V in 64-key chunks, cp.async
// double-buffered. Per 8-key subtile: QK mma -> exp -> P smem bounce -> PV mma.
#define QROWS 208
#define QS_STRIDE 52
#define KS_OFF 10816
#define KS_STRIDE 52
#define KS_BUFW 3328            // 64*52
#define VS_OFF 17472
#define VS_STRIDE 56
#define VS_BUFW 3584            // 64*56
#define PS_OFF 24640
#define PS_STRIDE 12
#define AT_SMEMW 27712          // words (110848 B)

__global__ void __launch_bounds__(256, 1) attn_mma_kernel(const float* __restrict__ qp)
{
    extern __shared__ uint32_t sm[];
    int tid = threadIdx.x;
    int bh = blockIdx.x;
    int b = bh >> 3, h = bh & 7;
    int wid = tid >> 5, lane = tid & 31;
    int fr = lane >> 2, fk = lane & 3;

    // warp M-tile assignment: warps 0..4 own 2 tiles, 5..7 own 1 (13 total)
    int tbase = (wid < 5) ? 2 * wid : (10 + (wid - 5));
    int cnt   = (wid < 5) ? 2 : 1;

    const float* kbase = g_k + (size_t)bh * N_ * DH_;
    const float* vbase = g_v + (size_t)bh * N_ * DH_;

    // ---- Q -> smem (tf32), pad rows zero ----
    for (int idx = tid; idx < QROWS * 48; idx += 256) {
        int m = idx / 48, d = idx - m * 48;
        float v = (m < M_) ? qp[((size_t)m * H_ + h) * DH_ + d] : 0.0f;
        sm[m * QS_STRIDE + d] = f2tf32(v);
    }

    // ---- prologue: chunk 0 -> buf 0 ----
    #pragma unroll
    for (int j = 0; j < 3; j++) {
        int cidx = tid + j * 256;               // 768 16B-chunks each
        int r = cidx / 12, cc = cidx - r * 12;
        cp16((uint32_t)__cvta_generic_to_shared(sm + KS_OFF + r * KS_STRIDE + cc * 4),
             (const float4*)kbase + cidx);
        cp16((uint32_t)__cvta_generic_to_shared(sm + VS_OFF + r * VS_STRIDE + cc * 4),
             (const float4*)vbase + cidx);
    }
    CP_COMMIT();
    __syncthreads();                            // Q visible

    // ---- Q fragments -> registers ----
    unsigned qf[2][6][4];
    for (int mt = 0; mt < cnt; mt++) {
        int r0 = (tbase + mt) * 16 + fr;
        #pragma unroll
        for (int kt = 0; kt < 6; kt++) {
            qf[mt][kt][0] = sm[r0 * QS_STRIDE + kt * 8 + fk];
            qf[mt][kt][1] = sm[(r0 + 8) * QS_STRIDE + kt * 8 + fk];
            qf[mt][kt][2] = sm[r0 * QS_STRIDE + kt * 8 + fk + 4];
            qf[mt][kt][3] = sm[(r0 + 8) * QS_STRIDE + kt * 8 + fk + 4];
        }
    }

    float oacc[2][6][4];
    #pragma unroll
    for (int i = 0; i < 2; i++)
        #pragma unroll
        for (int j = 0; j < 6; j++)
            #pragma unroll
            for (int r = 0; r < 4; r++) oacc[i][j][r] = 0.0f;
    float lsum[2][2] = {{0.f, 0.f}, {0.f, 0.f}};

    uint32_t ps_base = PS_OFF + wid * 32 * PS_STRIDE;

    for (int c = 0; c < 49; c++) {
        int buf = c & 1;
        if (c + 1 < 49) {
            int nb = buf ^ 1;
            const float4* ks = (const float4*)(kbase + (size_t)(c + 1) * 64 * DH_);
            const float4* vs = (const float4*)(vbase + (size_t)(c + 1) * 64 * DH_);
            #pragma unroll
            for (int j = 0; j < 3; j++) {
                int cidx = tid + j * 256;
                int r = cidx / 12, cc2 = cidx - r * 12;
                cp16((uint32_t)__cvta_generic_to_shared(
                         sm + KS_OFF + nb * KS_BUFW + r * KS_STRIDE + cc2 * 4),
                     ks + cidx);
                cp16((uint32_t)__cvta_generic_to_shared(
                         sm + VS_OFF + nb * VS_BUFW + r * VS_STRIDE + cc2 * 4),
                     vs + cidx);
            }
            CP_COMMIT();
            CP_WAIT1();
        } else {
            CP_WAIT0();
        }
        __syncthreads();

        const uint32_t* kb = sm + KS_OFF + buf * KS_BUFW;
        const uint32_t* vb = sm + VS_OFF + buf * VS_BUFW;

        for (int sub = 0; sub < 8; sub++) {
            // ---- QK ----
            float s[2][4];
            #pragma unroll
            for (int i = 0; i < 2; i++)
                #pragma unroll
                for (int r = 0; r < 4; r++) s[i][r] = 0.0f;
            #pragma unroll
            for (int kt = 0; kt < 6; kt++) {
                unsigned bb[2];
                bb[0] = kb[(sub * 8 + fr) * KS_STRIDE + kt * 8 + fk];      // raw f32 (HW trunc)
                bb[1] = kb[(sub * 8 + fr) * KS_STRIDE + kt * 8 + fk + 4];
                for (int mt = 0; mt < cnt; mt++)
                    mma_tf32(s[mt], qf[mt][kt], bb);
            }
            // ---- exp + P store + lsum ----
            for (int mt = 0; mt < cnt; mt++) {
                unsigned c0 = f2tf32(__expf(s[mt][0]));
                unsigned c1 = f2tf32(__expf(s[mt][1]));
                unsigned c2 = f2tf32(__expf(s[mt][2]));
                unsigned c3 = f2tf32(__expf(s[mt][3]));
                lsum[mt][0] += __uint_as_float(c0) + __uint_as_float(c1);
                lsum[mt][1] += __uint_as_float(c2) + __uint_as_float(c3);
                uint32_t a0 = ps_base + (mt * 16 + fr) * PS_STRIDE + 2 * fk;
                sm[a0] = c0; sm[a0 + 1] = c1;
                uint32_t a1 = ps_base + (mt * 16 + fr + 8) * PS_STRIDE + 2 * fk;
                sm[a1] = c2; sm[a1 + 1] = c3;
            }
            __syncwarp();
            // ---- P A-frags ----
            unsigned pa[2][4];
            for (int mt = 0; mt < cnt; mt++) {
                pa[mt][0] = sm[ps_base + (mt * 16 + fr) * PS_STRIDE + fk];
                pa[mt][1] = sm[ps_base + (mt * 16 + fr + 8) * PS_STRIDE + fk];
                pa[mt][2] = sm[ps_base + (mt * 16 + fr) * PS_STRIDE + fk + 4];
                pa[mt][3] = sm[ps_base + (mt * 16 + fr + 8) * PS_STRIDE + fk + 4];
            }
            __syncwarp();
            // ---- PV ----
            #pragma unroll
            for (int nt = 0; nt < 6; nt++) {
                unsigned vv[2];
                vv[0] = f2tf32(__uint_as_float(vb[(sub * 8 + fk) * VS_STRIDE + nt * 8 + fr]));
                vv[1] = f2tf32(__uint_as_float(vb[(sub * 8 + fk + 4) * VS_STRIDE + nt * 8 + fr]));
                for (int mt = 0; mt < cnt; mt++)
                    mma_tf32(oacc[mt][nt], pa[mt], vv);
            }
        }
        __syncthreads();
    }

    // ---- epilogue: row-sum reduce across fk quad, scale, store ----
    for (int mt = 0; mt < cnt; mt++) {
        #pragma unroll
        for (int hh = 0; hh < 2; hh++) {
            float l = lsum[mt][hh];
            l += __shfl_xor_sync(0xffffffffu, l, 1);
            l += __shfl_xor_sync(0xffffffffu, l, 2);
            float inv = 1.0f / l;
            int m = (tbase + mt) * 16 + fr + hh * 8;
            if (m < M_) {
                float* orow = g_ao + ((size_t)b * M_ + m) * C_ + h * DH_;
                #pragma unroll
                for (int nt = 0; nt < 6; nt++) {
                    float2 val;
                    val.x = oacc[mt][nt][hh * 2 + 0] * inv;
                    val.y = oacc[mt][nt][hh * 2 + 1] * inv;
                    *(float2*)(orow + nt * 8 + 2 * fk) = val;
                }
            }
        }
    }
}

// -------------------------------------------------------------- K4: proj GEMM
__global__ __launch_bounds__(256) void sgemm_proj_kernel(
    const float* __restrict__ W,
    const float* __restrict__ bias,
    float* __restrict__ out)
{
    __shared__ __align__(16) float As[8][136];
    __shared__ __align__(16) float Bs[8][136];

    int n0 = blockIdx.x * 128;
    int m0 = blockIdx.y * 128;
    int tid = threadIdx.x;
    int tx = tid & 15, ty = tid >> 4;
    int lrow = tid >> 1;
    int lk   = (tid & 1) * 4;

    const float* aptr = g_ao + (size_t)(m0 + lrow) * C_ + lk;
    const float* wptr = W    + (size_t)(n0 + lrow) * C_ + lk;

    float acc[8][8];
    #pragma unroll
    for (int i = 0; i < 8; i++)
        #pragma unroll
        for (int j = 0; j < 8; j++) acc[i][j] = 0.0f;

    for (int k0 = 0; k0 < C_; k0 += 8) {
        float4 av = *(const float4*)(aptr + k0);
        float4 bv = *(const float4*)(wptr + k0);
        __syncthreads();
        As[lk + 0][lrow] = av.x; As[lk + 1][lrow] = av.y;
        As[lk + 2][lrow] = av.z; As[lk + 3][lrow] = av.w;
        Bs[lk + 0][lrow] = bv.x; Bs[lk + 1][lrow] = bv.y;
        Bs[lk + 2][lrow] = bv.z; Bs[lk + 3][lrow] = bv.w;
        __syncthreads();
        #pragma unroll
        for (int kk = 0; kk < 8; kk++) {
            float a[8], bq[8];
            *(float4*)&a[0] = *(const float4*)&As[kk][ty * 4];
            *(float4*)&a[4] = *(const float4*)&As[kk][64 + ty * 4];
            *(float4*)&bq[0] = *(const float4*)&Bs[kk][tx * 4];
            *(float4*)&bq[4] = *(const float4*)&Bs[kk][64 + tx * 4];
            #pragma unroll
            for (int i = 0; i < 8; i++)
                #pragma unroll
                for (int j = 0; j < 8; j++)
                    acc[i][j] += a[i] * bq[j];
        }
    }

    #pragma unroll
    for (int i = 0; i < 8; i++) {
        int r = m0 + ((i < 4) ? (ty * 4 + i) : (64 + ty * 4 + i - 4));
        #pragma unroll
        for (int j = 0; j < 8; j++) {
            int c = n0 + ((j < 4) ? (tx * 4 + j) : (64 + tx * 4 + j - 4));
            out[(size_t)r * C_ + c] = acc[i][j] + bias[c];
        }
    }
}

// ----------------------------------------------------------------- launcher
extern "C" void kernel_launch(void* const* d_in, const int* in_sizes, int n_in,
                              void* d_out, int out_size)
{
    const float* x      = (const float*)d_in[0];
    const float* qp     = (const float*)d_in[1];
    const float* kv_w   = (const float*)d_in[2];
    const float* proj_w = (const float*)d_in[3];
    const float* proj_b = (const float*)d_in[4];
    const float* ln_w   = (const float*)d_in[5];
    const float* ln_b   = (const float*)d_in[6];
    float* out = (float*)d_out;

    cudaFuncSetAttribute(attn_mma_kernel,
                         cudaFuncAttributeMaxDynamicSharedMemorySize, AT_SMEMW * 4);

    ln_gelu_kernel<<<T_, 128>>>(x, ln_w, ln_b);

    dim3 g2(6, 784);
    mma_kv_kernel<<<g2, 256>>>(kv_w);

    attn_mma_kernel<<<B_ * H_, 256, AT_SMEMW * 4>>>(qp);

    dim3 g4(3, 49);
    sgemm_proj_kernel<<<g4, 256>>>(proj_w, proj_b, out);
}

// round 7
// speedup vs baseline: 3.3335x; 1.2836x over previous
#include <cuda_runtime.h>
#include <math.h>
#include <stdint.h>

// Problem dims
#define B_   32
#define N_   3136
#define C_   384
#define H_   8
#define DH_  48
#define M_   196
#define T_   (B_ * N_)          // 100352 tokens

// ---------------- scratch (static device globals; no runtime allocation) ---
__device__ float g_xg[T_ * C_];              // gelu(ln(x))        154 MB
__device__ float g_k [B_ * H_ * N_ * DH_];   // k in [b,h,n,d]     154 MB
__device__ float g_v [B_ * H_ * N_ * DH_];   // v in [b,h,n,d]     154 MB
__device__ float g_ao[B_ * M_ * C_];         // attn out [b,m,c]   9.6 MB

// ---------------------------------------------------------------- K1: LN+GELU
__global__ __launch_bounds__(128) void ln_gelu_kernel(
    const float* __restrict__ x,
    const float* __restrict__ lw,
    const float* __restrict__ lb)
{
    int t = blockIdx.x;
    const float* xr = x + (size_t)t * C_;
    float* outr = g_xg + (size_t)t * C_;
    int tid = threadIdx.x;

    float v0 = xr[tid], v1 = xr[tid + 128], v2 = xr[tid + 256];
    float s  = v0 + v1 + v2;
    float sq = v0 * v0 + v1 * v1 + v2 * v2;
    #pragma unroll
    for (int o = 16; o > 0; o >>= 1) {
        s  += __shfl_down_sync(0xffffffffu, s,  o);
        sq += __shfl_down_sync(0xffffffffu, sq, o);
    }
    __shared__ float ss[4], sqs[4];
    __shared__ float mu_s, rs_s;
    int w = tid >> 5;
    if ((tid & 31) == 0) { ss[w] = s; sqs[w] = sq; }
    __syncthreads();
    if (tid == 0) {
        float S  = ss[0] + ss[1] + ss[2] + ss[3];
        float SQ = sqs[0] + sqs[1] + sqs[2] + sqs[3];
        float mu  = S * (1.0f / C_);
        float var = SQ * (1.0f / C_) - mu * mu;
        mu_s = mu;
        rs_s = rsqrtf(var + 1e-6f);
    }
    __syncthreads();
    float mu = mu_s, rs = rs_s;

    #pragma unroll
    for (int i = 0; i < 3; i++) {
        int c = tid + i * 128;
        float v = (i == 0) ? v0 : ((i == 1) ? v1 : v2);
        float y = (v - mu) * rs * lw[c] + lb[c];
        float g = 0.5f * y * (1.0f + erff(y * 0.70710678118654752f));
        outr[c] = g;
    }
}

// ------------------------------------------------------ tf32 MMA helpers
__device__ __forceinline__ unsigned f2tf32(float f) {
    unsigned r;
    asm("cvt.rna.tf32.f32 %0, %1;" : "=r"(r) : "f"(f));
    return r;
}

__device__ __forceinline__ void mma_tf32(float* c, const unsigned* a, const unsigned* b) {
    asm volatile(
        "mma.sync.aligned.m16n8k8.row.col.f32.tf32.tf32.f32 "
        "{%0,%1,%2,%3}, {%4,%5,%6,%7}, {%8,%9}, {%0,%1,%2,%3};"
        : "+f"(c[0]), "+f"(c[1]), "+f"(c[2]), "+f"(c[3])
        : "r"(a[0]), "r"(a[1]), "r"(a[2]), "r"(a[3]),
          "r"(b[0]), "r"(b[1]));
}

__device__ __forceinline__ void cp16(uint32_t sa, const void* g) {
    asm volatile("cp.async.cg.shared.global [%0], [%1], 16;" :: "r"(sa), "l"(g));
}
#define CP_COMMIT() asm volatile("cp.async.commit_group;")
#define CP_WAIT1()  asm volatile("cp.async.wait_group 1;")
#define CP_WAIT0()  asm volatile("cp.async.wait_group 0;")

// ============= shared 3-stage pipelined tf32 GEMM core (128x128 CTA) =========
// A,B tiles [row][k] raw f32, stride 20 words (bank-conflict-free frags),
// k-chunk 16, 3 stages. 8 warps 2x4, warp tile 64x32.
#define GSTRIDE 20
#define GSTAGEW (128 * GSTRIDE)      // 2560 words per stage per matrix
#define GBOFF   (3 * GSTAGEW)        // 7680: B stages start
#define GSMEMB  (6 * GSTAGEW * 4)    // 61440 bytes

// issue cp.async for chunk c of A(row-major [m0+row][k]) and B([n0+row][k])
__device__ __forceinline__ void gemm_cp_chunk(
    float* sm, int stage, int tid, const float* Abase, const float* Bbase, int c)
{
    float* as = sm + stage * GSTAGEW;
    float* bs = sm + GBOFF + stage * GSTAGEW;
    #pragma unroll
    for (int j = 0; j < 2; j++) {
        int cidx = tid + j * 256;         // 0..511
        int row = cidx >> 2, kq = cidx & 3;
        cp16((uint32_t)__cvta_generic_to_shared(as + row * GSTRIDE + kq * 4),
             Abase + (size_t)row * C_ + c * 16 + kq * 4);
        cp16((uint32_t)__cvta_generic_to_shared(bs + row * GSTRIDE + kq * 4),
             Bbase + (size_t)row * C_ + c * 16 + kq * 4);
    }
    CP_COMMIT();
}

// mainloop body: accumulates into acc[4][4][4]
__device__ __forceinline__ void gemm_mainloop(
    float* sm, int tid, const float* Abase, const float* Bbase,
    float acc[4][4][4], int wm, int wn, int fr, int fk)
{
    gemm_cp_chunk(sm, 0, tid, Abase, Bbase, 0);
    gemm_cp_chunk(sm, 1, tid, Abase, Bbase, 1);

    for (int c = 0; c < 24; c++) {
        if (c >= 22) { CP_WAIT0(); } else { CP_WAIT1(); }
        __syncthreads();
        const float* As = sm + (c % 3) * GSTAGEW;
        const float* Bs = sm + GBOFF + (c % 3) * GSTAGEW;

        #pragma unroll
        for (int kp = 0; kp < 16; kp += 8) {
            unsigned af[4][4];
            #pragma unroll
            for (int mt = 0; mt < 4; mt++) {
                int rb = wm * 64 + mt * 16 + fr;
                af[mt][0] = f2tf32(As[rb * GSTRIDE + kp + fk]);
                af[mt][1] = f2tf32(As[(rb + 8) * GSTRIDE + kp + fk]);
                af[mt][2] = f2tf32(As[rb * GSTRIDE + kp + fk + 4]);
                af[mt][3] = f2tf32(As[(rb + 8) * GSTRIDE + kp + fk + 4]);
            }
            unsigned bf[4][2];
            #pragma unroll
            for (int nt = 0; nt < 4; nt++) {
                int cb = wn * 32 + nt * 8 + fr;
                bf[nt][0] = f2tf32(Bs[cb * GSTRIDE + kp + fk]);
                bf[nt][1] = f2tf32(Bs[cb * GSTRIDE + kp + fk + 4]);
            }
            #pragma unroll
            for (int mt = 0; mt < 4; mt++)
                #pragma unroll
                for (int nt = 0; nt < 4; nt++)
                    mma_tf32(acc[mt][nt], af[mt], bf[nt]);
        }

        if (c + 2 < 24)
            gemm_cp_chunk(sm, (c + 2) % 3, tid, Abase, Bbase, c + 2);
    }
}

// --------------------------------------------------------- K2: kv GEMM (tf32)
// out[t, j] = sum_c xg[t,c] * kv_w[j,c]; epilogue scatters to g_k/g_v [b,h,n,d].
__global__ void __launch_bounds__(256, 2) mma_kv_kernel(const float* __restrict__ W)
{
    extern __shared__ float sm[];
    int n0 = blockIdx.x * 128;   // 6 col tiles (x fastest -> A L2 reuse)
    int m0 = blockIdx.y * 128;
    int tid = threadIdx.x;
    int wid = tid >> 5, lane = tid & 31;
    int wm = wid >> 2, wn = wid & 3;
    int fr = lane >> 2, fk = lane & 3;

    float acc[4][4][4];
    #pragma unroll
    for (int i = 0; i < 4; i++)
        #pragma unroll
        for (int j = 0; j < 4; j++)
            #pragma unroll
            for (int r = 0; r < 4; r++) acc[i][j][r] = 0.0f;

    gemm_mainloop(sm, tid, g_xg + (size_t)m0 * C_, W + (size_t)n0 * C_,
                  acc, wm, wn, fr, fk);

    #pragma unroll
    for (int mt = 0; mt < 4; mt++) {
        #pragma unroll
        for (int half = 0; half < 2; half++) {
            int r  = m0 + wm * 64 + mt * 16 + fr + half * 8;
            int bb = r / N_;
            int nn = r - bb * N_;
            #pragma unroll
            for (int nt = 0; nt < 4; nt++) {
                int c  = n0 + wn * 32 + nt * 8 + fk * 2;
                int cc = (c >= C_) ? (c - C_) : c;
                int h  = cc / DH_;
                int d  = cc - h * DH_;
                float* dst = (c >= C_) ? g_v : g_k;
                float2 val;
                val.x = acc[mt][nt][half * 2 + 0];
                val.y = acc[mt][nt][half * 2 + 1];
                *(float2*)(dst + (((size_t)bb * H_ + h) * N_ + nn) * DH_ + d) = val;
            }
        }
    }
}

// -------------------------------------------------------------- K4: proj GEMM
// out[r, c] = sum_k g_ao[r,k] * proj_w[c,k] + bias[c];  M=6272, N=384, K=384
__global__ void __launch_bounds__(256, 2) mma_proj_kernel(
    const float* __restrict__ W,
    const float* __restrict__ bias,
    float* __restrict__ out)
{
    extern __shared__ float sm[];
    int n0 = blockIdx.x * 128;   // 3 tiles
    int m0 = blockIdx.y * 128;   // 49 tiles
    int tid = threadIdx.x;
    int wid = tid >> 5, lane = tid & 31;
    int wm = wid >> 2, wn = wid & 3;
    int fr = lane >> 2, fk = lane & 3;

    float acc[4][4][4];
    #pragma unroll
    for (int i = 0; i < 4; i++)
        #pragma unroll
        for (int j = 0; j < 4; j++)
            #pragma unroll
            for (int r = 0; r < 4; r++) acc[i][j][r] = 0.0f;

    gemm_mainloop(sm, tid, g_ao + (size_t)m0 * C_, W + (size_t)n0 * C_,
                  acc, wm, wn, fr, fk);

    #pragma unroll
    for (int mt = 0; mt < 4; mt++) {
        #pragma unroll
        for (int half = 0; half < 2; half++) {
            int r = m0 + wm * 64 + mt * 16 + fr + half * 8;
            #pragma unroll
            for (int nt = 0; nt < 4; nt++) {
                int c = n0 + wn * 32 + nt * 8 + fk * 2;
                float2 val;
                val.x = acc[mt][nt][half * 2 + 0] + bias[c];
                val.y = acc[mt][nt][half * 2 + 1] + bias[c + 1];
                *(float2*)(out + (size_t)r * C_ + c) = val;
            }
        }
    }
}

// ------------------------------------------------------------- K3: MMA attn
// One CTA (256 thr, 8 warps) per (b,h). Flash-style, tf32 mma.
#define QROWS 208
#define QS_STRIDE 52
#define KS_OFF 10816
#define KS_STRIDE 52
#define KS_BUFW 3328            // 64*52
#define VS_OFF 17472
#define VS_STRIDE 56
#define VS_BUFW 3584            // 64*56
#define PS_OFF 24640
#define PS_STRIDE 12
#define AT_SMEMW 27712          // words (110848 B)

__global__ void __launch_bounds__(256, 1) attn_mma_kernel(const float* __restrict__ qp)
{
    extern __shared__ uint32_t smw[];
    uint32_t* smv = smw;
    int tid = threadIdx.x;
    int bh = blockIdx.x;
    int b = bh >> 3, h = bh & 7;
    int wid = tid >> 5, lane = tid & 31;
    int fr = lane >> 2, fk = lane & 3;

    int tbase = (wid < 5) ? 2 * wid : (10 + (wid - 5));
    int cnt   = (wid < 5) ? 2 : 1;

    const float* kbase = g_k + (size_t)bh * N_ * DH_;
    const float* vbase = g_v + (size_t)bh * N_ * DH_;

    for (int idx = tid; idx < QROWS * 48; idx += 256) {
        int m = idx / 48, d = idx - m * 48;
        float v = (m < M_) ? qp[((size_t)m * H_ + h) * DH_ + d] : 0.0f;
        smv[m * QS_STRIDE + d] = f2tf32(v);
    }

    #pragma unroll
    for (int j = 0; j < 3; j++) {
        int cidx = tid + j * 256;
        int r = cidx / 12, cc = cidx - r * 12;
        cp16((uint32_t)__cvta_generic_to_shared(smv + KS_OFF + r * KS_STRIDE + cc * 4),
             (const float4*)kbase + cidx);
        cp16((uint32_t)__cvta_generic_to_shared(smv + VS_OFF + r * VS_STRIDE + cc * 4),
             (const float4*)vbase + cidx);
    }
    CP_COMMIT();
    __syncthreads();

    unsigned qf[2][6][4];
    for (int mt = 0; mt < cnt; mt++) {
        int r0 = (tbase + mt) * 16 + fr;
        #pragma unroll
        for (int kt = 0; kt < 6; kt++) {
            qf[mt][kt][0] = smv[r0 * QS_STRIDE + kt * 8 + fk];
            qf[mt][kt][1] = smv[(r0 + 8) * QS_STRIDE + kt * 8 + fk];
            qf[mt][kt][2] = smv[r0 * QS_STRIDE + kt * 8 + fk + 4];
            qf[mt][kt][3] = smv[(r0 + 8) * QS_STRIDE + kt * 8 + fk + 4];
        }
    }

    float oacc[2][6][4];
    #pragma unroll
    for (int i = 0; i < 2; i++)
        #pragma unroll
        for (int j = 0; j < 6; j++)
            #pragma unroll
            for (int r = 0; r < 4; r++) oacc[i][j][r] = 0.0f;
    float lsum[2][2] = {{0.f, 0.f}, {0.f, 0.f}};

    uint32_t ps_base = PS_OFF + wid * 32 * PS_STRIDE;

    for (int c = 0; c < 49; c++) {
        int buf = c & 1;
        if (c + 1 < 49) {
            int nb = buf ^ 1;
            const float4* ks = (const float4*)(kbase + (size_t)(c + 1) * 64 * DH_);
            const float4* vs = (const float4*)(vbase + (size_t)(c + 1) * 64 * DH_);
            #pragma unroll
            for (int j = 0; j < 3; j++) {
                int cidx = tid + j * 256;
                int r = cidx / 12, cc2 = cidx - r * 12;
                cp16((uint32_t)__cvta_generic_to_shared(
                         smv + KS_OFF + nb * KS_BUFW + r * KS_STRIDE + cc2 * 4),
                     ks + cidx);
                cp16((uint32_t)__cvta_generic_to_shared(
                         smv + VS_OFF + nb * VS_BUFW + r * VS_STRIDE + cc2 * 4),
                     vs + cidx);
            }
            CP_COMMIT();
            CP_WAIT1();
        } else {
            CP_WAIT0();
        }
        __syncthreads();

        const uint32_t* kb = smv + KS_OFF + buf * KS_BUFW;
        const uint32_t* vb = smv + VS_OFF + buf * VS_BUFW;

        for (int sub = 0; sub < 8; sub++) {
            float s[2][4];
            #pragma unroll
            for (int i = 0; i < 2; i++)
                #pragma unroll
                for (int r = 0; r < 4; r++) s[i][r] = 0.0f;
            #pragma unroll
            for (int kt = 0; kt < 6; kt++) {
                unsigned bb[2];
                bb[0] = kb[(sub * 8 + fr) * KS_STRIDE + kt * 8 + fk];
                bb[1] = kb[(sub * 8 + fr) * KS_STRIDE + kt * 8 + fk + 4];
                for (int mt = 0; mt < cnt; mt++)
                    mma_tf32(s[mt], qf[mt][kt], bb);
            }
            for (int mt = 0; mt < cnt; mt++) {
                unsigned c0 = f2tf32(__expf(s[mt][0]));
                unsigned c1 = f2tf32(__expf(s[mt][1]));
                unsigned c2 = f2tf32(__expf(s[mt][2]));
                unsigned c3 = f2tf32(__expf(s[mt][3]));
                lsum[mt][0] += __uint_as_float(c0) + __uint_as_float(c1);
                lsum[mt][1] += __uint_as_float(c2) + __uint_as_float(c3);
                uint32_t a0 = ps_base + (mt * 16 + fr) * PS_STRIDE + 2 * fk;
                smv[a0] = c0; smv[a0 + 1] = c1;
                uint32_t a1 = ps_base + (mt * 16 + fr + 8) * PS_STRIDE + 2 * fk;
                smv[a1] = c2; smv[a1 + 1] = c3;
            }
            __syncwarp();
            unsigned pa[2][4];
            for (int mt = 0; mt < cnt; mt++) {
                pa[mt][0] = smv[ps_base + (mt * 16 + fr) * PS_STRIDE + fk];
                pa[mt][1] = smv[ps_base + (mt * 16 + fr + 8) * PS_STRIDE + fk];
                pa[mt][2] = smv[ps_base + (mt * 16 + fr) * PS_STRIDE + fk + 4];
                pa[mt][3] = smv[ps_base + (mt * 16 + fr + 8) * PS_STRIDE + fk + 4];
            }
            __syncwarp();
            #pragma unroll
            for (int nt = 0; nt < 6; nt++) {
                unsigned vv[2];
                vv[0] = f2tf32(__uint_as_float(vb[(sub * 8 + fk) * VS_STRIDE + nt * 8 + fr]));
                vv[1] = f2tf32(__uint_as_float(vb[(sub * 8 + fk + 4) * VS_STRIDE + nt * 8 + fr]));
                for (int mt = 0; mt < cnt; mt++)
                    mma_tf32(oacc[mt][nt], pa[mt], vv);
            }
        }
        __syncthreads();
    }

    for (int mt = 0; mt < cnt; mt++) {
        #pragma unroll
        for (int hh = 0; hh < 2; hh++) {
            float l = lsum[mt][hh];
            l += __shfl_xor_sync(0xffffffffu, l, 1);
            l += __shfl_xor_sync(0xffffffffu, l, 2);
            float inv = 1.0f / l;
            int m = (tbase + mt) * 16 + fr + hh * 8;
            if (m < M_) {
                float* orow = g_ao + ((size_t)b * M_ + m) * C_ + h * DH_;
                #pragma unroll
                for (int nt = 0; nt < 6; nt++) {
                    float2 val;
                    val.x = oacc[mt][nt][hh * 2 + 0] * inv;
                    val.y = oacc[mt][nt][hh * 2 + 1] * inv;
                    *(float2*)(orow + nt * 8 + 2 * fk) = val;
                }
            }
        }
    }
}

// ----------------------------------------------------------------- launcher
extern "C" void kernel_launch(void* const* d_in, const int* in_sizes, int n_in,
                              void* d_out, int out_size)
{
    const float* x      = (const float*)d_in[0];
    const float* qp     = (const float*)d_in[1];
    const float* kv_w   = (const float*)d_in[2];
    const float* proj_w = (const float*)d_in[3];
    const float* proj_b = (const float*)d_in[4];
    const float* ln_w   = (const float*)d_in[5];
    const float* ln_b   = (const float*)d_in[6];
    float* out = (float*)d_out;

    cudaFuncSetAttribute(attn_mma_kernel,
                         cudaFuncAttributeMaxDynamicSharedMemorySize, AT_SMEMW * 4);
    cudaFuncSetAttribute(mma_kv_kernel,
                         cudaFuncAttributeMaxDynamicSharedMemorySize, GSMEMB);
    cudaFuncSetAttribute(mma_proj_kernel,
                         cudaFuncAttributeMaxDynamicSharedMemorySize, GSMEMB);

    ln_gelu_kernel<<<T_, 128>>>(x, ln_w, ln_b);

    dim3 g2(6, 784);
    mma_kv_kernel<<<g2, 256, GSMEMB>>>(kv_w);

    attn_mma_kernel<<<B_ * H_, 256, AT_SMEMW * 4>>>(qp);

    dim3 g4(3, 49);
    mma_proj_kernel<<<g4, 256, GSMEMB>>>(proj_w, proj_b, out);
}

// round 8
// speedup vs baseline: 4.1637x; 1.2490x over previous
#include <cuda_runtime.h>
#include <math.h>
#include <stdint.h>

// Problem dims
#define B_   32
#define N_   3136
#define C_   384
#define H_   8
#define DH_  48
#define M_   196
#define T_   (B_ * N_)          // 100352 tokens

// ---------------- scratch (static device globals; no runtime allocation) ---
__device__ float g_xg[T_ * C_];              // gelu(ln(x)), tf32-valued
__device__ float g_k [B_ * H_ * N_ * DH_];   // k [b,h,n,d], tf32-valued
__device__ float g_v [B_ * H_ * N_ * DH_];   // v [b,h,n,d], tf32-valued
__device__ float g_ao[B_ * M_ * C_];         // attn out [b,m,c], tf32-valued
__device__ float g_wkv[2 * C_ * C_];         // kv_w pre-rounded to tf32
__device__ float g_wpj[C_ * C_];             // proj_w pre-rounded to tf32

// ------------------------------------------------------ tf32 helpers
__device__ __forceinline__ unsigned f2tf32(float f) {
    unsigned r;
    asm("cvt.rna.tf32.f32 %0, %1;" : "=r"(r) : "f"(f));
    return r;
}
__device__ __forceinline__ float rtf32(float f) { return __uint_as_float(f2tf32(f)); }

__device__ __forceinline__ void mma_tf32(float* c, const unsigned* a, const unsigned* b) {
    asm volatile(
        "mma.sync.aligned.m16n8k8.row.col.f32.tf32.tf32.f32 "
        "{%0,%1,%2,%3}, {%4,%5,%6,%7}, {%8,%9}, {%0,%1,%2,%3};"
        : "+f"(c[0]), "+f"(c[1]), "+f"(c[2]), "+f"(c[3])
        : "r"(a[0]), "r"(a[1]), "r"(a[2]), "r"(a[3]),
          "r"(b[0]), "r"(b[1]));
}

__device__ __forceinline__ void cp16(uint32_t sa, const void* g) {
    asm volatile("cp.async.cg.shared.global [%0], [%1], 16;" :: "r"(sa), "l"(g));
}
#define CP_COMMIT() asm volatile("cp.async.commit_group;")
#define CP_WAIT1()  asm volatile("cp.async.wait_group 1;")
#define CP_WAIT0()  asm volatile("cp.async.wait_group 0;")

// ------------------------------------------------- K0: pre-round weights
__global__ __launch_bounds__(256) void round_w_kernel(
    const float* __restrict__ kv_w, const float* __restrict__ proj_w)
{
    int i = blockIdx.x * 256 + threadIdx.x;
    if (i < 2 * C_ * C_) g_wkv[i] = rtf32(kv_w[i]);
    if (i < C_ * C_)     g_wpj[i] = rtf32(proj_w[i]);
}

// ---------------------------------------------------------------- K1: LN+GELU
// One warp per token, float4 I/O, butterfly reduction. Output tf32-valued.
__global__ __launch_bounds__(256) void ln_gelu_kernel(
    const float* __restrict__ x,
    const float* __restrict__ lw,
    const float* __restrict__ lb)
{
    int t = (blockIdx.x * 256 + threadIdx.x) >> 5;   // token id (grid covers T_)
    int lane = threadIdx.x & 31;
    const float4* xr = (const float4*)(x + (size_t)t * C_);
    float4* outr = (float4*)(g_xg + (size_t)t * C_);

    float4 a = xr[lane], bq = xr[lane + 32], cq = xr[lane + 64];
    float s = a.x + a.y + a.z + a.w + bq.x + bq.y + bq.z + bq.w
            + cq.x + cq.y + cq.z + cq.w;
    float q = a.x*a.x + a.y*a.y + a.z*a.z + a.w*a.w
            + bq.x*bq.x + bq.y*bq.y + bq.z*bq.z + bq.w*bq.w
            + cq.x*cq.x + cq.y*cq.y + cq.z*cq.z + cq.w*cq.w;
    #pragma unroll
    for (int o = 16; o > 0; o >>= 1) {
        s += __shfl_xor_sync(0xffffffffu, s, o);
        q += __shfl_xor_sync(0xffffffffu, q, o);
    }
    float mu  = s * (1.0f / C_);
    float var = q * (1.0f / C_) - mu * mu;
    float rs  = rsqrtf(var + 1e-6f);

    const float4* lw4 = (const float4*)lw;
    const float4* lb4 = (const float4*)lb;
    #pragma unroll
    for (int j = 0; j < 3; j++) {
        float4 v = (j == 0) ? a : ((j == 1) ? bq : cq);
        float4 w = lw4[lane + j * 32];
        float4 bb = lb4[lane + j * 32];
        float4 o;
        float y;
        y = (v.x - mu) * rs * w.x + bb.x;
        o.x = rtf32(0.5f * y * (1.0f + erff(y * 0.70710678118654752f)));
        y = (v.y - mu) * rs * w.y + bb.y;
        o.y = rtf32(0.5f * y * (1.0f + erff(y * 0.70710678118654752f)));
        y = (v.z - mu) * rs * w.z + bb.z;
        o.z = rtf32(0.5f * y * (1.0f + erff(y * 0.70710678118654752f)));
        y = (v.w - mu) * rs * w.w + bb.w;
        o.w = rtf32(0.5f * y * (1.0f + erff(y * 0.70710678118654752f)));
        outr[lane + j * 32] = o;
    }
}

// ============= shared 3-stage pipelined tf32 GEMM core (128x128 CTA) =========
// A,B tiles [row][k], values already tf32-exact -> raw bit feed, NO cvt.
#define GSTRIDE 20
#define GSTAGEW (128 * GSTRIDE)      // 2560 words per stage per matrix
#define GBOFF   (3 * GSTAGEW)        // B stages start
#define GSMEMB  (6 * GSTAGEW * 4)    // 61440 bytes

__device__ __forceinline__ void gemm_cp_chunk(
    float* sm, int stage, int tid, const float* Abase, const float* Bbase, int c)
{
    float* as = sm + stage * GSTAGEW;
    float* bs = sm + GBOFF + stage * GSTAGEW;
    #pragma unroll
    for (int j = 0; j < 2; j++) {
        int cidx = tid + j * 256;
        int row = cidx >> 2, kq = cidx & 3;
        cp16((uint32_t)__cvta_generic_to_shared(as + row * GSTRIDE + kq * 4),
             Abase + (size_t)row * C_ + c * 16 + kq * 4);
        cp16((uint32_t)__cvta_generic_to_shared(bs + row * GSTRIDE + kq * 4),
             Bbase + (size_t)row * C_ + c * 16 + kq * 4);
    }
    CP_COMMIT();
}

__device__ __forceinline__ void gemm_mainloop(
    float* sm, int tid, const float* Abase, const float* Bbase,
    float acc[4][4][4], int wm, int wn, int fr, int fk)
{
    gemm_cp_chunk(sm, 0, tid, Abase, Bbase, 0);
    gemm_cp_chunk(sm, 1, tid, Abase, Bbase, 1);

    for (int c = 0; c < 24; c++) {
        if (c >= 22) { CP_WAIT0(); } else { CP_WAIT1(); }
        __syncthreads();
        const unsigned* As = (const unsigned*)(sm + (c % 3) * GSTAGEW);
        const unsigned* Bs = (const unsigned*)(sm + GBOFF + (c % 3) * GSTAGEW);

        #pragma unroll
        for (int kp = 0; kp < 16; kp += 8) {
            unsigned af[4][4];
            #pragma unroll
            for (int mt = 0; mt < 4; mt++) {
                int rb = wm * 64 + mt * 16 + fr;
                af[mt][0] = As[rb * GSTRIDE + kp + fk];
                af[mt][1] = As[(rb + 8) * GSTRIDE + kp + fk];
                af[mt][2] = As[rb * GSTRIDE + kp + fk + 4];
                af[mt][3] = As[(rb + 8) * GSTRIDE + kp + fk + 4];
            }
            unsigned bf[4][2];
            #pragma unroll
            for (int nt = 0; nt < 4; nt++) {
                int cb = wn * 32 + nt * 8 + fr;
                bf[nt][0] = Bs[cb * GSTRIDE + kp + fk];
                bf[nt][1] = Bs[cb * GSTRIDE + kp + fk + 4];
            }
            #pragma unroll
            for (int mt = 0; mt < 4; mt++)
                #pragma unroll
                for (int nt = 0; nt < 4; nt++)
                    mma_tf32(acc[mt][nt], af[mt], bf[nt]);
        }

        if (c + 2 < 24)
            gemm_cp_chunk(sm, (c + 2) % 3, tid, Abase, Bbase, c + 2);
    }
}

// --------------------------------------------------------- K2: kv GEMM (tf32)
__global__ void __launch_bounds__(256, 2) mma_kv_kernel()
{
    extern __shared__ float sm[];
    int n0 = blockIdx.x * 128;
    int m0 = blockIdx.y * 128;
    int tid = threadIdx.x;
    int wid = tid >> 5, lane = tid & 31;
    int wm = wid >> 2, wn = wid & 3;
    int fr = lane >> 2, fk = lane & 3;

    float acc[4][4][4];
    #pragma unroll
    for (int i = 0; i < 4; i++)
        #pragma unroll
        for (int j = 0; j < 4; j++)
            #pragma unroll
            for (int r = 0; r < 4; r++) acc[i][j][r] = 0.0f;

    gemm_mainloop(sm, tid, g_xg + (size_t)m0 * C_, g_wkv + (size_t)n0 * C_,
                  acc, wm, wn, fr, fk);

    #pragma unroll
    for (int mt = 0; mt < 4; mt++) {
        #pragma unroll
        for (int half = 0; half < 2; half++) {
            int r  = m0 + wm * 64 + mt * 16 + fr + half * 8;
            int bb = r / N_;
            int nn = r - bb * N_;
            #pragma unroll
            for (int nt = 0; nt < 4; nt++) {
                int c  = n0 + wn * 32 + nt * 8 + fk * 2;
                int cc = (c >= C_) ? (c - C_) : c;
                int h  = cc / DH_;
                int d  = cc - h * DH_;
                float* dst = (c >= C_) ? g_v : g_k;
                float2 val;
                val.x = rtf32(acc[mt][nt][half * 2 + 0]);   // tf32-exact for attn
                val.y = rtf32(acc[mt][nt][half * 2 + 1]);
                *(float2*)(dst + (((size_t)bb * H_ + h) * N_ + nn) * DH_ + d) = val;
            }
        }
    }
}

// -------------------------------------------------------------- K4: proj GEMM
__global__ void __launch_bounds__(256, 2) mma_proj_kernel(
    const float* __restrict__ bias,
    float* __restrict__ out)
{
    extern __shared__ float sm[];
    int n0 = blockIdx.x * 128;
    int m0 = blockIdx.y * 128;
    int tid = threadIdx.x;
    int wid = tid >> 5, lane = tid & 31;
    int wm = wid >> 2, wn = wid & 3;
    int fr = lane >> 2, fk = lane & 3;

    float acc[4][4][4];
    #pragma unroll
    for (int i = 0; i < 4; i++)
        #pragma unroll
        for (int j = 0; j < 4; j++)
            #pragma unroll
            for (int r = 0; r < 4; r++) acc[i][j][r] = 0.0f;

    gemm_mainloop(sm, tid, g_ao + (size_t)m0 * C_, g_wpj + (size_t)n0 * C_,
                  acc, wm, wn, fr, fk);

    #pragma unroll
    for (int mt = 0; mt < 4; mt++) {
        #pragma unroll
        for (int half = 0; half < 2; half++) {
            int r = m0 + wm * 64 + mt * 16 + fr + half * 8;
            #pragma unroll
            for (int nt = 0; nt < 4; nt++) {
                int c = n0 + wn * 32 + nt * 8 + fk * 2;
                float2 val;
                val.x = acc[mt][nt][half * 2 + 0] + bias[c];
                val.y = acc[mt][nt][half * 2 + 1] + bias[c + 1];
                *(float2*)(out + (size_t)r * C_ + c) = val;
            }
        }
    }
}

// ------------------------------------------------------------- K3: MMA attn
// One CTA (256 thr, 8 warps) per (b,h), 2 CTAs/SM. Static mt=0/1 unroll.
#define QROWS 208
#define QS_STRIDE 52
#define KS_OFF 10816
#define KS_STRIDE 52
#define KS_BUFW 3328            // 64*52
#define VS_OFF 17472
#define VS_STRIDE 56
#define VS_BUFW 3584            // 64*56
#define PS_OFF 24640
#define PS_STRIDE 12
#define AT_SMEMW 27712          // words (110848 B)

__global__ void __launch_bounds__(256, 2) attn_mma_kernel(const float* __restrict__ qp)
{
    extern __shared__ uint32_t smv[];
    int tid = threadIdx.x;
    int bh = blockIdx.x;
    int b = bh >> 3, h = bh & 7;
    int wid = tid >> 5, lane = tid & 31;
    int fr = lane >> 2, fk = lane & 3;

    // warps 0..4 own 2 M-tiles, warps 5..7 own 1 (13 tiles of 16 rows)
    int tbase = (wid < 5) ? 2 * wid : (10 + (wid - 5));
    bool two  = (wid < 5);

    const float* kbase = g_k + (size_t)bh * N_ * DH_;
    const float* vbase = g_v + (size_t)bh * N_ * DH_;

    for (int idx = tid; idx < QROWS * 48; idx += 256) {
        int m = idx / 48, d = idx - m * 48;
        float v = (m < M_) ? qp[((size_t)m * H_ + h) * DH_ + d] : 0.0f;
        smv[m * QS_STRIDE + d] = f2tf32(v);
    }

    #pragma unroll
    for (int j = 0; j < 3; j++) {
        int cidx = tid + j * 256;
        int r = cidx / 12, cc = cidx - r * 12;
        cp16((uint32_t)__cvta_generic_to_shared(smv + KS_OFF + r * KS_STRIDE + cc * 4),
             (const float4*)kbase + cidx);
        cp16((uint32_t)__cvta_generic_to_shared(smv + VS_OFF + r * VS_STRIDE + cc * 4),
             (const float4*)vbase + cidx);
    }
    CP_COMMIT();
    __syncthreads();

    unsigned qf[2][6][4];
    #pragma unroll
    for (int mt = 0; mt < 2; mt++) {
        if (mt == 0 || two) {
            int r0 = (tbase + mt) * 16 + fr;
            #pragma unroll
            for (int kt = 0; kt < 6; kt++) {
                qf[mt][kt][0] = smv[r0 * QS_STRIDE + kt * 8 + fk];
                qf[mt][kt][1] = smv[(r0 + 8) * QS_STRIDE + kt * 8 + fk];
                qf[mt][kt][2] = smv[r0 * QS_STRIDE + kt * 8 + fk + 4];
                qf[mt][kt][3] = smv[(r0 + 8) * QS_STRIDE + kt * 8 + fk + 4];
            }
        }
    }

    float oacc[2][6][4];
    #pragma unroll
    for (int i = 0; i < 2; i++)
        #pragma unroll
        for (int j = 0; j < 6; j++)
            #pragma unroll
            for (int r = 0; r < 4; r++) oacc[i][j][r] = 0.0f;
    float lsum[2][2] = {{0.f, 0.f}, {0.f, 0.f}};

    uint32_t ps_base = PS_OFF + wid * 32 * PS_STRIDE;

    for (int c = 0; c < 49; c++) {
        int buf = c & 1;
        if (c + 1 < 49) {
            int nb = buf ^ 1;
            const float4* ks = (const float4*)(kbase + (size_t)(c + 1) * 64 * DH_);
            const float4* vs = (const float4*)(vbase + (size_t)(c + 1) * 64 * DH_);
            #pragma unroll
            for (int j = 0; j < 3; j++) {
                int cidx = tid + j * 256;
                int r = cidx / 12, cc2 = cidx - r * 12;
                cp16((uint32_t)__cvta_generic_to_shared(
                         smv + KS_OFF + nb * KS_BUFW + r * KS_STRIDE + cc2 * 4),
                     ks + cidx);
                cp16((uint32_t)__cvta_generic_to_shared(
                         smv + VS_OFF + nb * VS_BUFW + r * VS_STRIDE + cc2 * 4),
                     vs + cidx);
            }
            CP_COMMIT();
            CP_WAIT1();
        } else {
            CP_WAIT0();
        }
        __syncthreads();

        const uint32_t* kb = smv + KS_OFF + buf * KS_BUFW;
        const uint32_t* vb = smv + VS_OFF + buf * VS_BUFW;

        for (int sub = 0; sub < 8; sub++) {
            // ---- QK (K values tf32-exact -> raw feed) ----
            float s0[4] = {0.f, 0.f, 0.f, 0.f};
            float s1[4] = {0.f, 0.f, 0.f, 0.f};
            #pragma unroll
            for (int kt = 0; kt < 6; kt++) {
                unsigned bb[2];
                bb[0] = kb[(sub * 8 + fr) * KS_STRIDE + kt * 8 + fk];
                bb[1] = kb[(sub * 8 + fr) * KS_STRIDE + kt * 8 + fk + 4];
                mma_tf32(s0, qf[0][kt], bb);
                if (two) mma_tf32(s1, qf[1][kt], bb);
            }
            // ---- exp + P store + lsum ----
            {
                unsigned c0 = f2tf32(__expf(s0[0]));
                unsigned c1 = f2tf32(__expf(s0[1]));
                unsigned c2 = f2tf32(__expf(s0[2]));
                unsigned c3 = f2tf32(__expf(s0[3]));
                lsum[0][0] += __uint_as_float(c0) + __uint_as_float(c1);
                lsum[0][1] += __uint_as_float(c2) + __uint_as_float(c3);
                uint32_t a0 = ps_base + fr * PS_STRIDE + 2 * fk;
                smv[a0] = c0; smv[a0 + 1] = c1;
                uint32_t a1 = ps_base + (fr + 8) * PS_STRIDE + 2 * fk;
                smv[a1] = c2; smv[a1 + 1] = c3;
            }
            if (two) {
                unsigned c0 = f2tf32(__expf(s1[0]));
                unsigned c1 = f2tf32(__expf(s1[1]));
                unsigned c2 = f2tf32(__expf(s1[2]));
                unsigned c3 = f2tf32(__expf(s1[3]));
                lsum[1][0] += __uint_as_float(c0) + __uint_as_float(c1);
                lsum[1][1] += __uint_as_float(c2) + __uint_as_float(c3);
                uint32_t a0 = ps_base + (16 + fr) * PS_STRIDE + 2 * fk;
                smv[a0] = c0; smv[a0 + 1] = c1;
                uint32_t a1 = ps_base + (16 + fr + 8) * PS_STRIDE + 2 * fk;
                smv[a1] = c2; smv[a1 + 1] = c3;
            }
            __syncwarp();
            // ---- P A-frags ----
            unsigned pa[2][4];
            pa[0][0] = smv[ps_base + fr * PS_STRIDE + fk];
            pa[0][1] = smv[ps_base + (fr + 8) * PS_STRIDE + fk];
            pa[0][2] = smv[ps_base + fr * PS_STRIDE + fk + 4];
            pa[0][3] = smv[ps_base + (fr + 8) * PS_STRIDE + fk + 4];
            if (two) {
                pa[1][0] = smv[ps_base + (16 + fr) * PS_STRIDE + fk];
                pa[1][1] = smv[ps_base + (16 + fr + 8) * PS_STRIDE + fk];
                pa[1][2] = smv[ps_base + (16 + fr) * PS_STRIDE + fk + 4];
                pa[1][3] = smv[ps_base + (16 + fr + 8) * PS_STRIDE + fk + 4];
            }
            __syncwarp();
            // ---- PV (V values tf32-exact -> raw feed) ----
            #pragma unroll
            for (int nt = 0; nt < 6; nt++) {
                unsigned vv[2];
                vv[0] = vb[(sub * 8 + fk) * VS_STRIDE + nt * 8 + fr];
                vv[1] = vb[(sub * 8 + fk + 4) * VS_STRIDE + nt * 8 + fr];
                mma_tf32(oacc[0][nt], pa[0], vv);
                if (two) mma_tf32(oacc[1][nt], pa[1], vv);
            }
        }
        __syncthreads();
    }

    // ---- epilogue ----
    #pragma unroll
    for (int mt = 0; mt < 2; mt++) {
        if (mt == 0 || two) {
            #pragma unroll
            for (int hh = 0; hh < 2; hh++) {
                float l = lsum[mt][hh];
                l += __shfl_xor_sync(0xffffffffu, l, 1);
                l += __shfl_xor_sync(0xffffffffu, l, 2);
                float inv = 1.0f / l;
                int m = (tbase + mt) * 16 + fr + hh * 8;
                if (m < M_) {
                    float* orow = g_ao + ((size_t)b * M_ + m) * C_ + h * DH_;
                    #pragma unroll
                    for (int nt = 0; nt < 6; nt++) {
                        float2 val;
                        val.x = rtf32(oacc[mt][nt][hh * 2 + 0] * inv);  // tf32-exact for proj
                        val.y = rtf32(oacc[mt][nt][hh * 2 + 1] * inv);
                        *(float2*)(orow + nt * 8 + 2 * fk) = val;
                    }
                }
            }
        }
    }
}

// ----------------------------------------------------------------- launcher
extern "C" void kernel_launch(void* const* d_in, const int* in_sizes, int n_in,
                              void* d_out, int out_size)
{
    const float* x      = (const float*)d_in[0];
    const float* qp     = (const float*)d_in[1];
    const float* kv_w   = (const float*)d_in[2];
    const float* proj_w = (const float*)d_in[3];
    const float* proj_b = (const float*)d_in[4];
    const float* ln_w   = (const float*)d_in[5];
    const float* ln_b   = (const float*)d_in[6];
    float* out = (float*)d_out;

    cudaFuncSetAttribute(attn_mma_kernel,
                         cudaFuncAttributeMaxDynamicSharedMemorySize, AT_SMEMW * 4);
    cudaFuncSetAttribute(mma_kv_kernel,
                         cudaFuncAttributeMaxDynamicSharedMemorySize, GSMEMB);
    cudaFuncSetAttribute(mma_proj_kernel,
                         cudaFuncAttributeMaxDynamicSharedMemorySize, GSMEMB);

    round_w_kernel<<<(2 * C_ * C_ + 255) / 256, 256>>>(kv_w, proj_w);

    ln_gelu_kernel<<<T_ / 8, 256>>>(x, ln_w, ln_b);

    dim3 g2(6, 784);
    mma_kv_kernel<<<g2, 256, GSMEMB>>>();

    attn_mma_kernel<<<B_ * H_, 256, AT_SMEMW * 4>>>(qp);

    dim3 g4(3, 49);
    mma_proj_kernel<<<g4, 256, GSMEMB>>>(proj_b, out);
}